// round 11
// baseline (speedup 1.0000x reference)
#include <cuda_runtime.h>

#define KSEG 512
#define DFEAT 256
#define HID 64
#define OUTC 32
#define MAXN 1048576
#define NB   1184         // hist/scatter blocks (8 per SM on 148 SMs)
#define SPLIT 4           // reduce CTAs per segment
#define CPT 5             // blocks per thread in seg-scan (ceil(1184/256))

__device__ int g_bh[KSEG * NB];      // transposed: [seg][block]; counts then bases
__device__ int g_count[KSEG];
__device__ int g_offsets[KSEG + 1];
__device__ int g_perm[MAXN];
__device__ int g_done[KSEG];         // re-zeroed by finalize each replay
__device__ float g_part[SPLIT * KSEG * DFEAT];   // feature partial sums
__device__ float g_cpart[KSEG * 3];  // coord sums (atomic); re-zeroed by finalize

// ---------------------------------------------------------------- pass A: histogram + coord accumulation
__global__ void __launch_bounds__(256) hist_kernel(const int* __restrict__ ids,
                                                   const float4* __restrict__ coords4,
                                                   const float* __restrict__ coords,
                                                   int n, int chunk) {
    __shared__ int sh[KSEG];
    __shared__ float scx[KSEG], scy[KSEG], scz[KSEG];
    int t = threadIdx.x;
    for (int i = t; i < KSEG; i += 256) { sh[i] = 0; scx[i] = 0.f; scy[i] = 0.f; scz[i] = 0.f; }
    __syncthreads();
    int b = blockIdx.x;
    int lo = b * chunk;                 // chunk is a multiple of 4
    int hi = min(lo + chunk, n);
    int nv = (hi - lo) >> 2;            // full int4 groups
    const int4* ids4 = (const int4*)(ids + lo);
    int cb0 = (3 * lo) >> 2;            // float4 index of coords[3*lo]
    for (int i = t; i < nv; i += 256) {
        int4 v = ids4[i];
        int cb = cb0 + 3 * i;
        float4 f0 = coords4[cb];
        float4 f1 = coords4[cb + 1];
        float4 f2 = coords4[cb + 2];
        if (v.x >= 0) { atomicAdd(&sh[v.x], 1); atomicAdd(&scx[v.x], f0.x); atomicAdd(&scy[v.x], f0.y); atomicAdd(&scz[v.x], f0.z); }
        if (v.y >= 0) { atomicAdd(&sh[v.y], 1); atomicAdd(&scx[v.y], f0.w); atomicAdd(&scy[v.y], f1.x); atomicAdd(&scz[v.y], f1.y); }
        if (v.z >= 0) { atomicAdd(&sh[v.z], 1); atomicAdd(&scx[v.z], f1.z); atomicAdd(&scy[v.z], f1.w); atomicAdd(&scz[v.z], f2.x); }
        if (v.w >= 0) { atomicAdd(&sh[v.w], 1); atomicAdd(&scx[v.w], f2.y); atomicAdd(&scy[v.w], f2.z); atomicAdd(&scz[v.w], f2.w); }
    }
    for (int i = lo + (nv << 2) + t; i < hi; i += 256) {  // tail
        int s = ids[i];
        if (s >= 0) {
            atomicAdd(&sh[s], 1);
            atomicAdd(&scx[s], coords[3 * i + 0]);
            atomicAdd(&scy[s], coords[3 * i + 1]);
            atomicAdd(&scz[s], coords[3 * i + 2]);
        }
    }
    __syncthreads();
    for (int i = t; i < KSEG; i += 256) {
        int c = sh[i];
        g_bh[i * NB + b] = c;
        if (c) {
            atomicAdd(&g_cpart[i * 3 + 0], scx[i]);
            atomicAdd(&g_cpart[i * 3 + 1], scy[i]);
            atomicAdd(&g_cpart[i * 3 + 2], scz[i]);
        }
    }
}

// ---------------------------------------------------------------- pass B: per-segment scan over blocks
// grid = KSEG, 256 threads; transposed layout -> coalesced contiguous reads.
__global__ void __launch_bounds__(256) segscan_kernel() {
    int s = blockIdx.x;
    int t = threadIdx.x;
    int b0 = t * CPT;
    int v[CPT];
    int local = 0;
#pragma unroll
    for (int k = 0; k < CPT; k++) {
        int b = b0 + k;
        v[k] = (b < NB) ? g_bh[s * NB + b] : 0;
        local += v[k];
    }
    __shared__ int sh[256];
    sh[t] = local;
    __syncthreads();
    for (int off = 1; off < 256; off <<= 1) {
        int tmp = (t >= off) ? sh[t - off] : 0;
        int cur = sh[t];
        __syncthreads();
        sh[t] = cur + tmp;
        __syncthreads();
    }
    int run = sh[t] - local;   // exclusive prefix
#pragma unroll
    for (int k = 0; k < CPT; k++) {
        int b = b0 + k;
        if (b < NB) g_bh[s * NB + b] = run;
        run += v[k];
    }
    if (t == 255) g_count[s] = sh[255];
}

// ---------------------------------------------------------------- pass C: scatter (in-CTA offset scan)
__global__ void __launch_bounds__(256) scatter_kernel(const int* __restrict__ ids, int n, int chunk) {
    __shared__ int soff[KSEG];
    __shared__ int spair[256];
    int t = threadIdx.x;
    int b = blockIdx.x;
    int c0 = g_count[2 * t];
    int c1 = g_count[2 * t + 1];
    int pair = c0 + c1;
    spair[t] = pair;
    __syncthreads();
    for (int off = 1; off < 256; off <<= 1) {
        int tmp = (t >= off) ? spair[t - off] : 0;
        int cur = spair[t];
        __syncthreads();
        spair[t] = cur + tmp;
        __syncthreads();
    }
    int excl = spair[t] - pair;
    soff[2 * t]     = excl;
    soff[2 * t + 1] = excl + c0;
    __syncthreads();
    if (b == 0) {
        g_offsets[2 * t]     = soff[2 * t];
        g_offsets[2 * t + 1] = soff[2 * t + 1];
        if (t == 255) g_offsets[KSEG] = spair[255];
    }
    __shared__ int cur[KSEG];
    for (int i = t; i < KSEG; i += 256)
        cur[i] = soff[i] + g_bh[i * NB + b];
    __syncthreads();
    int lo = b * chunk;
    int hi = min(lo + chunk, n);
    int nv = (hi - lo) >> 2;
    const int4* ids4 = (const int4*)(ids + lo);
    for (int i = t; i < nv; i += 256) {
        int4 v = ids4[i];
        int base = lo + (i << 2);
        if (v.x >= 0) g_perm[atomicAdd(&cur[v.x], 1)] = base;
        if (v.y >= 0) g_perm[atomicAdd(&cur[v.y], 1)] = base + 1;
        if (v.z >= 0) g_perm[atomicAdd(&cur[v.z], 1)] = base + 2;
        if (v.w >= 0) g_perm[atomicAdd(&cur[v.w], 1)] = base + 3;
    }
    for (int i = lo + (nv << 2) + t; i < hi; i += 256) {
        int s = ids[i];
        if (s >= 0) g_perm[atomicAdd(&cur[s], 1)] = i;
    }
}

// ---------------------------------------------------------------- split reduce + fused finalize/MLP
// Feature gather loop identical to R10 winner; coords removed.
__global__ void __launch_bounds__(256, 8) reduce_kernel(const float4* __restrict__ feat4,
                                                        const float* __restrict__ W1,
                                                        const float* __restrict__ W2,
                                                        const float* __restrict__ W3,
                                                        const float* __restrict__ b3,
                                                        float* __restrict__ emb,
                                                        float* __restrict__ cent,
                                                        float* __restrict__ out) {
    int bid = blockIdx.x;
    int s = bid >> 2;          // segment
    int p = bid & (SPLIT - 1); // part
    int start = g_offsets[s];
    int end   = g_offsets[s + 1];
    int len   = end - start;
    int per   = (len + SPLIT - 1) / SPLIT;
    int lo = start + p * per;
    int hi = min(lo + per, end);

    int t  = threadIdx.x;
    int cg = t & 63;    // column group: cols [4cg, 4cg+3]
    int rs = t >> 6;    // row slot 0..3

    float4 acc = make_float4(0.f, 0.f, 0.f, 0.f);
    int j = lo + rs;
    for (; j + 12 < hi; j += 16) {
        int i0 = g_perm[j];
        int i1 = g_perm[j + 4];
        int i2 = g_perm[j + 8];
        int i3 = g_perm[j + 12];
        float4 v0 = __ldcs(&feat4[(size_t)i0 * 64 + cg]);
        float4 v1 = __ldcs(&feat4[(size_t)i1 * 64 + cg]);
        float4 v2 = __ldcs(&feat4[(size_t)i2 * 64 + cg]);
        float4 v3 = __ldcs(&feat4[(size_t)i3 * 64 + cg]);
        acc.x += (v0.x + v1.x) + (v2.x + v3.x);
        acc.y += (v0.y + v1.y) + (v2.y + v3.y);
        acc.z += (v0.z + v1.z) + (v2.z + v3.z);
        acc.w += (v0.w + v1.w) + (v2.w + v3.w);
    }
    for (; j < hi; j += 4) {
        int i0 = g_perm[j];
        float4 v0 = __ldcs(&feat4[(size_t)i0 * 64 + cg]);
        acc.x += v0.x; acc.y += v0.y; acc.z += v0.z; acc.w += v0.w;
    }

    __shared__ float4 shv[256];
    shv[t] = acc;
    __syncthreads();
    if (rs == 0) {
        float4 a = shv[cg], b = shv[cg + 64], c = shv[cg + 128], d = shv[cg + 192];
        float4 r;
        r.x = (a.x + b.x) + (c.x + d.x);
        r.y = (a.y + b.y) + (c.y + d.y);
        r.z = (a.z + b.z) + (c.z + d.z);
        r.w = (a.w + b.w) + (c.w + d.w);
        ((float4*)g_part)[((size_t)p * KSEG + s) * 64 + cg] = r;
    }

    // ---- last-block-done finalize ----
    __shared__ int slast;
    __threadfence();
    __syncthreads();
    if (t == 0) slast = (atomicAdd(&g_done[s], 1) == SPLIT - 1) ? 1 : 0;
    __syncthreads();
    if (!slast) return;

    float denom = 1.0f / (float)(len > 0 ? len : 1);
    __shared__ float e[DFEAT];
    float v = 0.f;
#pragma unroll
    for (int q = 0; q < SPLIT; q++)
        v += g_part[((size_t)q * KSEG + s) * DFEAT + t];
    v *= denom;
    e[t] = v;
    emb[(size_t)s * DFEAT + t] = v;

    if (t < 3) {
        cent[s * 3 + t] = g_cpart[s * 3 + t] * denom;
        g_cpart[s * 3 + t] = 0.f;   // re-arm for next graph replay
    }
    if (t == 0) g_done[s] = 0;      // re-arm for next graph replay
    __syncthreads();

    __shared__ float h1[HID];
    __shared__ float h2[HID];
    if (t < HID) {
        float a = 0.f;
#pragma unroll 8
        for (int k = 0; k < DFEAT; k++) a += e[k] * W1[k * HID + t];
        h1[t] = fmaxf(a, 0.f);
    }
    __syncthreads();
    if (t < HID) {
        float b = 0.f;
#pragma unroll 8
        for (int k = 0; k < HID; k++) b += h1[k] * W2[k * HID + t];
        h2[t] = fmaxf(b, 0.f);
    }
    __syncthreads();
    if (t < OUTC) {
        float c = b3[t];
#pragma unroll 8
        for (int k = 0; k < HID; k++) c += h2[k] * W3[k * OUTC + t];
        out[(size_t)s * OUTC + t] = c;
    }
}

// ---------------------------------------------------------------- launch
extern "C" void kernel_launch(void* const* d_in, const int* in_sizes, int n_in,
                              void* d_out, int out_size) {
    const float* feat   = (const float*)d_in[0];
    const float* coords = (const float*)d_in[1];
    const int*   ids    = (const int*)d_in[2];

    int wi = 3;
    if (n_in >= 8 && in_sizes[3] == 1) wi = 4;
    const float* W1 = (const float*)d_in[wi + 0];
    const float* W2 = (const float*)d_in[wi + 1];
    const float* W3 = (const float*)d_in[wi + 2];
    const float* b3 = (const float*)d_in[wi + 3];

    int n = in_sizes[0] / DFEAT;
    int chunk = ((n + NB * 4 - 1) / (NB * 4)) * 4;   // multiple of 4 for int4

    float* out  = (float*)d_out;
    float* emb  = out;                           // [K, 256]
    float* cent = out + (size_t)KSEG * DFEAT;    // [K, 3]
    float* mlp  = cent + (size_t)KSEG * 3;       // [K, 32]
    (void)out_size;

    hist_kernel<<<NB, 256>>>(ids, (const float4*)coords, coords, n, chunk);
    segscan_kernel<<<KSEG, 256>>>();
    scatter_kernel<<<NB, 256>>>(ids, n, chunk);
    reduce_kernel<<<KSEG * SPLIT, 256>>>((const float4*)feat,
                                         W1, W2, W3, b3, emb, cent, mlp);
}

// round 12
// speedup vs baseline: 1.2627x; 1.2627x over previous
#include <cuda_runtime.h>

#define KSEG 512
#define DFEAT 256
#define HID 64
#define OUTC 32
#define MAXN 1048576
#define NB   592          // hist/scatter blocks (4 per SM on 148 SMs)
#define SPLIT 4           // reduce CTAs per segment
#define CPT 3             // blocks per thread in seg-scan (ceil(592/256))

__device__ int g_blockhist[NB * KSEG];   // [block][seg]: counts then bases
__device__ int g_count[KSEG];
__device__ int g_offsets[KSEG + 1];
__device__ int g_perm[MAXN];
__device__ int g_done[KSEG];             // re-armed by finalize each replay
__device__ float g_part[SPLIT * KSEG * DFEAT];   // feature partial sums
__device__ float g_cblk[3 * KSEG * NB];  // per-block coord sums, [(3s+c)][block]

// ---------------------------------------------------------------- pass A: per-block histogram (int4) — R10 proven
__global__ void __launch_bounds__(256) hist_kernel(const int* __restrict__ ids, int n, int chunk) {
    __shared__ int sh[KSEG];
    for (int i = threadIdx.x; i < KSEG; i += 256) sh[i] = 0;
    __syncthreads();
    int b = blockIdx.x;
    int lo = b * chunk;                 // chunk is a multiple of 4
    int hi = min(lo + chunk, n);
    int nv = (hi - lo) >> 2;            // full int4s
    const int4* ids4 = (const int4*)(ids + lo);
    for (int i = threadIdx.x; i < nv; i += 256) {
        int4 v = ids4[i];
        if (v.x >= 0) atomicAdd(&sh[v.x], 1);
        if (v.y >= 0) atomicAdd(&sh[v.y], 1);
        if (v.z >= 0) atomicAdd(&sh[v.z], 1);
        if (v.w >= 0) atomicAdd(&sh[v.w], 1);
    }
    for (int i = lo + (nv << 2) + threadIdx.x; i < hi; i += 256) {
        int s = ids[i];
        if (s >= 0) atomicAdd(&sh[s], 1);
    }
    __syncthreads();
    for (int i = threadIdx.x; i < KSEG; i += 256)
        g_blockhist[b * KSEG + i] = sh[i];
}

// ---------------------------------------------------------------- pass B: per-segment scan over blocks — R10 proven
__global__ void __launch_bounds__(256) segscan_kernel() {
    int s = blockIdx.x;
    int t = threadIdx.x;
    int b0 = t * CPT;
    int v[CPT];
    int local = 0;
#pragma unroll
    for (int k = 0; k < CPT; k++) {
        int b = b0 + k;
        v[k] = (b < NB) ? g_blockhist[b * KSEG + s] : 0;
        local += v[k];
    }
    __shared__ int sh[256];
    sh[t] = local;
    __syncthreads();
    for (int off = 1; off < 256; off <<= 1) {
        int tmp = (t >= off) ? sh[t - off] : 0;
        int cur = sh[t];
        __syncthreads();
        sh[t] = cur + tmp;
        __syncthreads();
    }
    int run = sh[t] - local;   // exclusive prefix
#pragma unroll
    for (int k = 0; k < CPT; k++) {
        int b = b0 + k;
        if (b < NB) g_blockhist[b * KSEG + s] = run;
        run += v[k];
    }
    if (t == 255) g_count[s] = sh[255];
}

// ---------------------------------------------------------------- pass C: scatter + coord accumulation
__global__ void __launch_bounds__(256) scatter_kernel(const int* __restrict__ ids,
                                                      const float4* __restrict__ coords4,
                                                      const float* __restrict__ coords,
                                                      int n, int chunk) {
    __shared__ int soff[KSEG];
    __shared__ int spair[256];
    __shared__ float scx[KSEG], scy[KSEG], scz[KSEG];
    int t = threadIdx.x;
    int b = blockIdx.x;
    // exclusive segment-offset scan (redundant per CTA; g_count is L2-hot)
    int c0 = g_count[2 * t];
    int c1 = g_count[2 * t + 1];
    int pair = c0 + c1;
    spair[t] = pair;
    scx[2 * t] = 0.f; scx[2 * t + 1] = 0.f;
    scy[2 * t] = 0.f; scy[2 * t + 1] = 0.f;
    scz[2 * t] = 0.f; scz[2 * t + 1] = 0.f;
    __syncthreads();
    for (int off = 1; off < 256; off <<= 1) {
        int tmp = (t >= off) ? spair[t - off] : 0;
        int cur = spair[t];
        __syncthreads();
        spair[t] = cur + tmp;
        __syncthreads();
    }
    int excl = spair[t] - pair;
    soff[2 * t]     = excl;
    soff[2 * t + 1] = excl + c0;
    __syncthreads();
    if (b == 0) {
        g_offsets[2 * t]     = soff[2 * t];
        g_offsets[2 * t + 1] = soff[2 * t + 1];
        if (t == 255) g_offsets[KSEG] = spair[255];
    }
    __shared__ int cur[KSEG];
    for (int i = t; i < KSEG; i += 256)
        cur[i] = soff[i] + g_blockhist[b * KSEG + i];
    __syncthreads();
    int lo = b * chunk;
    int hi = min(lo + chunk, n);
    int nv = (hi - lo) >> 2;
    const int4* ids4 = (const int4*)(ids + lo);
    int cb0 = (3 * lo) >> 2;            // float4 index of coords[3*lo] (chunk%4==0)
    for (int i = t; i < nv; i += 256) {
        int4 v = ids4[i];
        int base = lo + (i << 2);
        int cb = cb0 + 3 * i;
        float4 f0 = coords4[cb];
        float4 f1 = coords4[cb + 1];
        float4 f2 = coords4[cb + 2];
        if (v.x >= 0) {
            g_perm[atomicAdd(&cur[v.x], 1)] = base;
            atomicAdd(&scx[v.x], f0.x); atomicAdd(&scy[v.x], f0.y); atomicAdd(&scz[v.x], f0.z);
        }
        if (v.y >= 0) {
            g_perm[atomicAdd(&cur[v.y], 1)] = base + 1;
            atomicAdd(&scx[v.y], f0.w); atomicAdd(&scy[v.y], f1.x); atomicAdd(&scz[v.y], f1.y);
        }
        if (v.z >= 0) {
            g_perm[atomicAdd(&cur[v.z], 1)] = base + 2;
            atomicAdd(&scx[v.z], f1.z); atomicAdd(&scy[v.z], f1.w); atomicAdd(&scz[v.z], f2.x);
        }
        if (v.w >= 0) {
            g_perm[atomicAdd(&cur[v.w], 1)] = base + 3;
            atomicAdd(&scx[v.w], f2.y); atomicAdd(&scy[v.w], f2.z); atomicAdd(&scz[v.w], f2.w);
        }
    }
    for (int i = lo + (nv << 2) + t; i < hi; i += 256) {  // tail
        int s = ids[i];
        if (s >= 0) {
            g_perm[atomicAdd(&cur[s], 1)] = i;
            atomicAdd(&scx[s], coords[3 * i + 0]);
            atomicAdd(&scy[s], coords[3 * i + 1]);
            atomicAdd(&scz[s], coords[3 * i + 2]);
        }
    }
    __syncthreads();
    // per-block coord sums: transposed so finalize reads are coalesced
    for (int i = t; i < KSEG; i += 256) {
        g_cblk[(3 * i + 0) * NB + b] = scx[i];
        g_cblk[(3 * i + 1) * NB + b] = scy[i];
        g_cblk[(3 * i + 2) * NB + b] = scz[i];
    }
}

// ---------------------------------------------------------------- split reduce + fused finalize/MLP
// Feature gather loop identical to R11 (proven 88.4us).
__global__ void __launch_bounds__(256, 8) reduce_kernel(const float4* __restrict__ feat4,
                                                        const float* __restrict__ W1,
                                                        const float* __restrict__ W2,
                                                        const float* __restrict__ W3,
                                                        const float* __restrict__ b3,
                                                        float* __restrict__ emb,
                                                        float* __restrict__ cent,
                                                        float* __restrict__ out) {
    int bid = blockIdx.x;
    int s = bid >> 2;          // segment
    int p = bid & (SPLIT - 1); // part
    int start = g_offsets[s];
    int end   = g_offsets[s + 1];
    int len   = end - start;
    int per   = (len + SPLIT - 1) / SPLIT;
    int lo = start + p * per;
    int hi = min(lo + per, end);

    int t  = threadIdx.x;
    int cg = t & 63;    // column group: cols [4cg, 4cg+3]
    int rs = t >> 6;    // row slot 0..3

    float4 acc = make_float4(0.f, 0.f, 0.f, 0.f);
    int j = lo + rs;
    for (; j + 12 < hi; j += 16) {
        int i0 = g_perm[j];
        int i1 = g_perm[j + 4];
        int i2 = g_perm[j + 8];
        int i3 = g_perm[j + 12];
        float4 v0 = __ldcs(&feat4[(size_t)i0 * 64 + cg]);
        float4 v1 = __ldcs(&feat4[(size_t)i1 * 64 + cg]);
        float4 v2 = __ldcs(&feat4[(size_t)i2 * 64 + cg]);
        float4 v3 = __ldcs(&feat4[(size_t)i3 * 64 + cg]);
        acc.x += (v0.x + v1.x) + (v2.x + v3.x);
        acc.y += (v0.y + v1.y) + (v2.y + v3.y);
        acc.z += (v0.z + v1.z) + (v2.z + v3.z);
        acc.w += (v0.w + v1.w) + (v2.w + v3.w);
    }
    for (; j < hi; j += 4) {
        int i0 = g_perm[j];
        float4 v0 = __ldcs(&feat4[(size_t)i0 * 64 + cg]);
        acc.x += v0.x; acc.y += v0.y; acc.z += v0.z; acc.w += v0.w;
    }

    __shared__ float4 shv[256];
    shv[t] = acc;
    __syncthreads();
    if (rs == 0) {
        float4 a = shv[cg], b = shv[cg + 64], c = shv[cg + 128], d = shv[cg + 192];
        float4 r;
        r.x = (a.x + b.x) + (c.x + d.x);
        r.y = (a.y + b.y) + (c.y + d.y);
        r.z = (a.z + b.z) + (c.z + d.z);
        r.w = (a.w + b.w) + (c.w + d.w);
        ((float4*)g_part)[((size_t)p * KSEG + s) * 64 + cg] = r;
    }

    // ---- last-block-done finalize ----
    __shared__ int slast;
    __threadfence();
    __syncthreads();
    if (t == 0) slast = (atomicAdd(&g_done[s], 1) == SPLIT - 1) ? 1 : 0;
    __syncthreads();
    if (!slast) return;

    float denom = 1.0f / (float)(len > 0 ? len : 1);
    __shared__ float e[DFEAT];
    float v = 0.f;
#pragma unroll
    for (int q = 0; q < SPLIT; q++)
        v += g_part[((size_t)q * KSEG + s) * DFEAT + t];
    v *= denom;
    e[t] = v;
    emb[(size_t)s * DFEAT + t] = v;
    if (t == 0) g_done[s] = 0;      // re-arm for next graph replay

    // coords: coalesced NB-contiguous reads per component, tree-reduce
    {
        float v0 = 0.f, v1 = 0.f, v2 = 0.f;
        for (int b = t; b < NB; b += 256) {
            v0 += g_cblk[(3 * s + 0) * NB + b];
            v1 += g_cblk[(3 * s + 1) * NB + b];
            v2 += g_cblk[(3 * s + 2) * NB + b];
        }
        __syncthreads();   // shv reuse safe
        shv[t] = make_float4(v0, v1, v2, 0.f);
        __syncthreads();
        for (int off = 128; off > 0; off >>= 1) {
            if (t < off) {
                shv[t].x += shv[t + off].x;
                shv[t].y += shv[t + off].y;
                shv[t].z += shv[t + off].z;
            }
            __syncthreads();
        }
        if (t < 3) {
            float c = (t == 0) ? shv[0].x : (t == 1) ? shv[0].y : shv[0].z;
            cent[s * 3 + t] = c * denom;
        }
    }
    __syncthreads();

    __shared__ float h1[HID];
    __shared__ float h2[HID];
    if (t < HID) {
        float a = 0.f;
#pragma unroll 8
        for (int k = 0; k < DFEAT; k++) a += e[k] * W1[k * HID + t];
        h1[t] = fmaxf(a, 0.f);
    }
    __syncthreads();
    if (t < HID) {
        float b = 0.f;
#pragma unroll 8
        for (int k = 0; k < HID; k++) b += h1[k] * W2[k * HID + t];
        h2[t] = fmaxf(b, 0.f);
    }
    __syncthreads();
    if (t < OUTC) {
        float c = b3[t];
#pragma unroll 8
        for (int k = 0; k < HID; k++) c += h2[k] * W3[k * OUTC + t];
        out[(size_t)s * OUTC + t] = c;
    }
}

// ---------------------------------------------------------------- launch
extern "C" void kernel_launch(void* const* d_in, const int* in_sizes, int n_in,
                              void* d_out, int out_size) {
    const float* feat   = (const float*)d_in[0];
    const float* coords = (const float*)d_in[1];
    const int*   ids    = (const int*)d_in[2];

    int wi = 3;
    if (n_in >= 8 && in_sizes[3] == 1) wi = 4;
    const float* W1 = (const float*)d_in[wi + 0];
    const float* W2 = (const float*)d_in[wi + 1];
    const float* W3 = (const float*)d_in[wi + 2];
    const float* b3 = (const float*)d_in[wi + 3];

    int n = in_sizes[0] / DFEAT;
    int chunk = ((n + NB * 4 - 1) / (NB * 4)) * 4;   // multiple of 4 for int4

    float* out  = (float*)d_out;
    float* emb  = out;                           // [K, 256]
    float* cent = out + (size_t)KSEG * DFEAT;    // [K, 3]
    float* mlp  = cent + (size_t)KSEG * 3;       // [K, 32]
    (void)out_size;

    hist_kernel<<<NB, 256>>>(ids, n, chunk);
    segscan_kernel<<<KSEG, 256>>>();
    scatter_kernel<<<NB, 256>>>(ids, (const float4*)coords, coords, n, chunk);
    reduce_kernel<<<KSEG * SPLIT, 256>>>((const float4*)feat,
                                         W1, W2, W3, b3, emb, cent, mlp);
}